// round 3
// baseline (speedup 1.0000x reference)
#include <cuda_runtime.h>
#include <math.h>

// B=32, J=16, L=4096, MU_P=0.15, MASK_ID=103
#define ROW_LEN   4096
#define THREADS   512
#define EPT       8
#define MASK_ID_F 103.0f
#define FULLMASK  0xFFFFFFFFu

// Order-preserving float -> uint32 transform (monotone increasing).
__device__ __forceinline__ unsigned int f2ord(float f) {
    unsigned int u = __float_as_uint(f);
    return (u & 0x80000000u) ? ~u : (u | 0x80000000u);
}

__global__ void __launch_bounds__(THREADS, 4)
gumbel_topk_mask_kernel(const int*   __restrict__ ids,
                        const float* __restrict__ msk2,   // (rows, 2*L)
                        const float* __restrict__ uu,     // (rows, L)
                        float*       __restrict__ out,    // (3, rows, L)
                        int N)
{
    __shared__ unsigned int hist[4][256];   // one per radix pass, cleared once
    __shared__ unsigned int s_prefix;
    __shared__ int          s_kk;
    __shared__ int          s_warpsum[16];

    const int t    = threadIdx.x;
    const int lane = t & 31;
    const int warp = t >> 5;
    const int row  = blockIdx.x;
    const long base = (long)row * ROW_LEN;

    const float* wrow = msk2 + (long)row * (2 * ROW_LEN);
    const float* urow = uu   + base;
    const int*   irow = ids  + base;

    // Clear all 4 histograms once (1024 words, 2 per thread)
    ((unsigned int*)hist)[t]          = 0u;
    ((unsigned int*)hist)[t + THREADS] = 0u;

    // ---- Phase 1: load, compute gumbel-perturbed scores, build sortable keys
    float4 w0 = reinterpret_cast<const float4*>(wrow)[t * 2 + 0];
    float4 w1 = reinterpret_cast<const float4*>(wrow)[t * 2 + 1];
    float4 u0 = reinterpret_cast<const float4*>(urow)[t * 2 + 0];
    float4 u1 = reinterpret_cast<const float4*>(urow)[t * 2 + 1];

    float wv[EPT] = {w0.x, w0.y, w0.z, w0.w, w1.x, w1.y, w1.z, w1.w};
    float uv[EPT] = {u0.x, u0.y, u0.z, u0.w, u1.x, u1.y, u1.z, u1.w};

    unsigned int mykeys[EPT];
    #pragma unroll
    for (int j = 0; j < EPT; j++) {
        unsigned int key = 0u;
        if (wv[j] > 0.0f) {
            float g     = -logf(-logf(uv[j]));
            float score = logf(fmaxf(wv[j], 1e-30f)) + g;
            key = f2ord(score);          // finite -> key in (0, 0xFFFFFFFF)
        }
        mykeys[j] = key;
    }
    __syncthreads();   // hist cleared, keys ready

    // ---- Phase 2: 4-pass radix-select of k-th largest key.
    // Aggregated smem atomics: lanes sharing a digit elect one leader.
    unsigned int prefixReg = 0u;
    int          kkReg     = 0;

    #pragma unroll
    for (int pass = 0; pass < 4; pass++) {
        const int shift = 24 - 8 * pass;
        const unsigned int himask = (pass == 0) ? 0u : (0xFFFFFFFFu << (shift + 8));

        #pragma unroll
        for (int j = 0; j < EPT; j++) {
            unsigned int key = mykeys[j];
            bool q = (pass == 0) ? (key != 0u)
                                 : ((key & himask) == prefixReg);
            unsigned int m = __ballot_sync(FULLMASK, q);
            if (q) {
                unsigned int d = (key >> shift) & 255u;
                unsigned int peers = __match_any_sync(m, d);
                if (lane == (__ffs(peers) - 1))
                    atomicAdd(&hist[pass][d], (unsigned int)__popc(peers));
            }
        }
        __syncthreads();

        if (warp == 0) {
            // lane owns 8 consecutive bins; suffix sums warp-locally
            unsigned int v[8], lsuf[8];
            #pragma unroll
            for (int i = 0; i < 8; i++) v[i] = hist[pass][lane * 8 + i];
            unsigned int tot = 0u;
            #pragma unroll
            for (int i = 7; i >= 0; i--) { tot += v[i]; lsuf[i] = tot; }

            unsigned int run = tot;
            #pragma unroll
            for (int off = 1; off < 32; off <<= 1) {
                unsigned int o = __shfl_down_sync(FULLMASK, run, off);
                if (lane + off < 32) run += o;
            }
            unsigned int above = run - tot;   // sum over lanes > lane

            int kkPass;
            if (pass == 0) {
                unsigned int cnt = __shfl_sync(FULLMASK, run, 0);   // total nonzero
                kkPass = (int)floorf(0.15f * (float)cnt);
                if (lane == 0 && kkPass <= 0) { s_prefix = 0xFFFFFFFFu; s_kk = 0; }
            } else {
                kkPass = kkReg;
            }

            if (kkPass > 0) {
                #pragma unroll
                for (int i = 0; i < 8; i++) {
                    unsigned int suf = lsuf[i] + above;   // count(byte >= bin)
                    unsigned int cgt = suf - v[i];        // count(byte >  bin)
                    if ((int)cgt < kkPass && kkPass <= (int)suf) {
                        s_prefix = prefixReg | ((unsigned int)(lane * 8 + i) << shift);
                        s_kk     = kkPass - (int)cgt;
                    }
                }
            }
        }
        __syncthreads();
        prefixReg = s_prefix;
        kkReg     = s_kk;
    }

    const unsigned int T = prefixReg;   // k-th largest key (0xFFFFFFFF if k==0)
    const int need_eq    = kkReg;       // # of key==T to take, lowest index first

    // ---- Phase 3: stable tie-break — exclusive scan of (key==T) counts
    int myEq = 0;
    #pragma unroll
    for (int j = 0; j < EPT; j++) myEq += (mykeys[j] == T) ? 1 : 0;

    int incl = myEq;
    #pragma unroll
    for (int off = 1; off < 32; off <<= 1) {
        int o = __shfl_up_sync(FULLMASK, incl, off);
        if (lane >= off) incl += o;
    }
    if (lane == 31) s_warpsum[warp] = incl;
    __syncthreads();
    if (warp == 0 && lane < 16) {
        int v  = s_warpsum[lane];
        int sc = v;
        #pragma unroll
        for (int off = 1; off < 16; off <<= 1) {
            int o = __shfl_up_sync(0x0000FFFFu, sc, off);
            if (lane >= off) sc += o;
        }
        s_warpsum[lane] = sc - v;     // exclusive warp offset
    }
    __syncthreads();
    int running = s_warpsum[warp] + (incl - myEq);

    // ---- Phase 4: selection + outputs
    int4 i0 = reinterpret_cast<const int4*>(irow)[t * 2 + 0];
    int4 i1 = reinterpret_cast<const int4*>(irow)[t * 2 + 1];
    int iv[EPT] = {i0.x, i0.y, i0.z, i0.w, i1.x, i1.y, i1.z, i1.w};

    float oid[EPT], om[EPT], onm[EPT];
    #pragma unroll
    for (int j = 0; j < EPT; j++) {
        bool sel = false;
        unsigned int key = mykeys[j];
        if (key > T) sel = true;
        else if (key == T) { sel = (running < need_eq); running++; }
        oid[j] = sel ? MASK_ID_F : (float)iv[j];
        om[j]  = sel ? 1.0f : 0.0f;
        onm[j] = sel ? -1.0f : -0.0f;
    }

    float4* o_ids = reinterpret_cast<float4*>(out + base);
    float4* o_m   = reinterpret_cast<float4*>(out + (long)N + base);
    float4* o_nm  = reinterpret_cast<float4*>(out + 2L * (long)N + base);
    o_ids[t * 2 + 0] = make_float4(oid[0], oid[1], oid[2], oid[3]);
    o_ids[t * 2 + 1] = make_float4(oid[4], oid[5], oid[6], oid[7]);
    o_m  [t * 2 + 0] = make_float4(om[0],  om[1],  om[2],  om[3]);
    o_m  [t * 2 + 1] = make_float4(om[4],  om[5],  om[6],  om[7]);
    o_nm [t * 2 + 0] = make_float4(onm[0], onm[1], onm[2], onm[3]);
    o_nm [t * 2 + 1] = make_float4(onm[4], onm[5], onm[6], onm[7]);
}

extern "C" void kernel_launch(void* const* d_in, const int* in_sizes, int n_in,
                              void* d_out, int out_size)
{
    const int*   ids  = (const int*)d_in[0];
    const float* msk2 = (const float*)d_in[1];
    const float* u    = (const float*)d_in[2];
    float*       out  = (float*)d_out;

    const int N    = in_sizes[0];
    const int rows = N / ROW_LEN;

    gumbel_topk_mask_kernel<<<rows, THREADS>>>(ids, msk2, u, out, N);
}

// round 4
// speedup vs baseline: 1.2922x; 1.2922x over previous
#include <cuda_runtime.h>
#include <math.h>

// B=32, J=16, L=4096, MU_P=0.15, MASK_ID=103
#define ROW_LEN   4096
#define THREADS   512
#define EPT       8
#define MASK_ID_F 103.0f
#define FULLMASK  0xFFFFFFFFu

__global__ void __launch_bounds__(THREADS)
gumbel_topk_mask_kernel(const int*   __restrict__ ids,
                        const float* __restrict__ msk2,   // (rows, 2*L)
                        const float* __restrict__ uu,     // (rows, L)
                        float*       __restrict__ out,    // (3, rows, L)
                        int N)
{
    __shared__ unsigned int hist[4][256];   // one per radix pass, cleared once
    __shared__ unsigned int s_prefix;
    __shared__ int          s_kk;
    __shared__ int          s_warpsum[16];

    const int t    = threadIdx.x;
    const int lane = t & 31;
    const int warp = t >> 5;
    const int row  = blockIdx.x;
    const long base = (long)row * ROW_LEN;

    const float* wrow = msk2 + (long)row * (2 * ROW_LEN);
    const float* urow = uu   + base;
    const int*   irow = ids  + base;

    // Clear all 4 histograms once (1024 words, 2 per thread)
    ((unsigned int*)hist)[t]           = 0u;
    ((unsigned int*)hist)[t + THREADS] = 0u;

    // ---- Phase 1: build sortable keys.
    // score = log(max(w,1e-30)) - log(-log u) = log( max(w,1e-30) / (-log u) ),
    // log monotone  =>  order by r = max(w,1e-30)/(-log u) directly.
    // r > 0 always, so key = bits(r) | 0x80000000 is order-preserving; key 0 = excluded.
    float4 w0 = reinterpret_cast<const float4*>(wrow)[t * 2 + 0];
    float4 w1 = reinterpret_cast<const float4*>(wrow)[t * 2 + 1];
    float4 u0 = reinterpret_cast<const float4*>(urow)[t * 2 + 0];
    float4 u1 = reinterpret_cast<const float4*>(urow)[t * 2 + 1];

    float wv[EPT] = {w0.x, w0.y, w0.z, w0.w, w1.x, w1.y, w1.z, w1.w};
    float uv[EPT] = {u0.x, u0.y, u0.z, u0.w, u1.x, u1.y, u1.z, u1.w};

    unsigned int mykeys[EPT];
    #pragma unroll
    for (int j = 0; j < EPT; j++) {
        unsigned int key = 0u;
        if (wv[j] > 0.0f) {
            float tneg = -logf(uv[j]);                    // > 0 since u < 1
            float r    = fmaxf(wv[j], 1e-30f) / tneg;     // > 0, finite
            key = __float_as_uint(r) | 0x80000000u;
        }
        mykeys[j] = key;
    }
    __syncthreads();   // hist cleared, keys ready

    // ---- Phase 2: 4-pass radix-select of k-th largest key (plain smem atomics)
    unsigned int prefixReg = 0u;
    int          kkReg     = 0;

    #pragma unroll
    for (int pass = 0; pass < 4; pass++) {
        const int shift = 24 - 8 * pass;

        if (pass == 0) {
            #pragma unroll
            for (int j = 0; j < EPT; j++) {
                unsigned int key = mykeys[j];
                if (key != 0u) atomicAdd(&hist[0][key >> 24], 1u);
            }
        } else {
            const unsigned int himask = 0xFFFFFFFFu << (shift + 8);
            #pragma unroll
            for (int j = 0; j < EPT; j++) {
                unsigned int key = mykeys[j];
                if ((key & himask) == prefixReg)
                    atomicAdd(&hist[pass][(key >> shift) & 255u], 1u);
            }
        }
        __syncthreads();

        if (warp == 0) {
            // lane owns 8 consecutive bins; warp-local suffix sums
            unsigned int v[8], lsuf[8];
            #pragma unroll
            for (int i = 0; i < 8; i++) v[i] = hist[pass][lane * 8 + i];
            unsigned int tot = 0u;
            #pragma unroll
            for (int i = 7; i >= 0; i--) { tot += v[i]; lsuf[i] = tot; }

            unsigned int run = tot;
            #pragma unroll
            for (int off = 1; off < 32; off <<= 1) {
                unsigned int o = __shfl_down_sync(FULLMASK, run, off);
                if (lane + off < 32) run += o;
            }
            unsigned int above = run - tot;   // sum over lanes > lane

            int kkPass;
            if (pass == 0) {
                unsigned int cnt = __shfl_sync(FULLMASK, run, 0);   // total nonzero
                kkPass = (int)floorf(0.15f * (float)cnt);
                if (lane == 0 && kkPass <= 0) { s_prefix = 0xFFFFFFFFu; s_kk = 0; }
            } else {
                kkPass = kkReg;
            }

            if (kkPass > 0) {
                #pragma unroll
                for (int i = 0; i < 8; i++) {
                    unsigned int suf = lsuf[i] + above;   // count(byte >= bin)
                    unsigned int cgt = suf - v[i];        // count(byte >  bin)
                    if ((int)cgt < kkPass && kkPass <= (int)suf) {
                        s_prefix = prefixReg | ((unsigned int)(lane * 8 + i) << shift);
                        s_kk     = kkPass - (int)cgt;
                    }
                }
            }
        }
        __syncthreads();
        prefixReg = s_prefix;
        kkReg     = s_kk;
    }

    const unsigned int T = prefixReg;   // k-th largest key (0xFFFFFFFF if k==0)
    const int need_eq    = kkReg;       // # of key==T to take, lowest index first

    // ---- Phase 3: stable tie-break — exclusive scan of (key==T) counts
    int myEq = 0;
    #pragma unroll
    for (int j = 0; j < EPT; j++) myEq += (mykeys[j] == T) ? 1 : 0;

    int incl = myEq;
    #pragma unroll
    for (int off = 1; off < 32; off <<= 1) {
        int o = __shfl_up_sync(FULLMASK, incl, off);
        if (lane >= off) incl += o;
    }
    if (lane == 31) s_warpsum[warp] = incl;
    __syncthreads();
    if (warp == 0 && lane < 16) {
        int v  = s_warpsum[lane];
        int sc = v;
        #pragma unroll
        for (int off = 1; off < 16; off <<= 1) {
            int o = __shfl_up_sync(0x0000FFFFu, sc, off);
            if (lane >= off) sc += o;
        }
        s_warpsum[lane] = sc - v;     // exclusive warp offset
    }
    __syncthreads();
    int running = s_warpsum[warp] + (incl - myEq);

    // ---- Phase 4: selection + outputs
    int4 i0 = reinterpret_cast<const int4*>(irow)[t * 2 + 0];
    int4 i1 = reinterpret_cast<const int4*>(irow)[t * 2 + 1];
    int iv[EPT] = {i0.x, i0.y, i0.z, i0.w, i1.x, i1.y, i1.z, i1.w};

    float oid[EPT], om[EPT], onm[EPT];
    #pragma unroll
    for (int j = 0; j < EPT; j++) {
        bool sel = false;
        unsigned int key = mykeys[j];
        if (key > T) sel = true;
        else if (key == T) { sel = (running < need_eq); running++; }
        oid[j] = sel ? MASK_ID_F : (float)iv[j];
        om[j]  = sel ? 1.0f : 0.0f;
        onm[j] = sel ? -1.0f : -0.0f;
    }

    float4* o_ids = reinterpret_cast<float4*>(out + base);
    float4* o_m   = reinterpret_cast<float4*>(out + (long)N + base);
    float4* o_nm  = reinterpret_cast<float4*>(out + 2L * (long)N + base);
    o_ids[t * 2 + 0] = make_float4(oid[0], oid[1], oid[2], oid[3]);
    o_ids[t * 2 + 1] = make_float4(oid[4], oid[5], oid[6], oid[7]);
    o_m  [t * 2 + 0] = make_float4(om[0],  om[1],  om[2],  om[3]);
    o_m  [t * 2 + 1] = make_float4(om[4],  om[5],  om[6],  om[7]);
    o_nm [t * 2 + 0] = make_float4(onm[0], onm[1], onm[2], onm[3]);
    o_nm [t * 2 + 1] = make_float4(onm[4], onm[5], onm[6], onm[7]);
}

extern "C" void kernel_launch(void* const* d_in, const int* in_sizes, int n_in,
                              void* d_out, int out_size)
{
    const int*   ids  = (const int*)d_in[0];
    const float* msk2 = (const float*)d_in[1];
    const float* u    = (const float*)d_in[2];
    float*       out  = (float*)d_out;

    const int N    = in_sizes[0];
    const int rows = N / ROW_LEN;

    gumbel_topk_mask_kernel<<<rows, THREADS>>>(ids, msk2, u, out, N);
}